// round 3
// baseline (speedup 1.0000x reference)
#include <cuda_runtime.h>

#define DT_F (1.0f/64.0f)
#define NSTEPS 64
#define NK 32
#define RTOT 16384
#define RAYS_PER_BLOCK 64
#define NTHREADS 1024
#define NBLOCKS (RTOT / RAYS_PER_BLOCK)         // 256
// dynamic smem: 4096 float4 template tile + 32*12 floats of per-prim affine
#define SMEM_BYTES (4096 * 16 + NK * 12 * 4)

__global__ void __launch_bounds__(NTHREADS, 1)
raymarch_kernel(const float* __restrict__ raypos,
                const float* __restrict__ raydir,
                const float* __restrict__ tminmax,
                const float* __restrict__ primpos,
                const float* __restrict__ primrot,
                const float* __restrict__ primscale,
                const float* __restrict__ tpl_g,
                float* __restrict__ out)
{
    extern __shared__ float4 sm[];
    float4* tpl = sm;                      // [16][16][16] voxels, 4 channels each
    float*  Mc  = (float*)(sm + 4096);     // [32][12]: 3 rows of (m0,m1,m2,c)

    const int tid  = threadIdx.x;
    const int sg   = tid & 15;             // step-group 0..15 (4 steps each)
    const int rayl = tid >> 4;             // local ray 0..63
    const int r    = blockIdx.x * RAYS_PER_BLOCK + rayl;

    const float rpx = raypos[3*r+0], rpy = raypos[3*r+1], rpz = raypos[3*r+2];
    const float rdx = raydir[3*r+0], rdy = raydir[3*r+1], rdz = raydir[3*r+2];
    const float tmn = tminmax[2*r+0], tmx = tminmax[2*r+1];

    // Per-prim affine: yloc_i = M[i]·pos - c_i, M[i][j] = scale_i * rot[i][j]
    if (tid < NK) {
        const int k = tid;
        const float ppx = primpos[3*k+0], ppy = primpos[3*k+1], ppz = primpos[3*k+2];
        #pragma unroll
        for (int i = 0; i < 3; i++) {
            const float s  = primscale[3*k+i];
            const float m0 = s * primrot[9*k+3*i+0];
            const float m1 = s * primrot[9*k+3*i+1];
            const float m2 = s * primrot[9*k+3*i+2];
            Mc[12*k+4*i+0] = m0;
            Mc[12*k+4*i+1] = m1;
            Mc[12*k+4*i+2] = m2;
            Mc[12*k+4*i+3] = m0*ppx + m1*ppy + m2*ppz;
        }
    }

    float4 acc[4];
    #pragma unroll
    for (int j = 0; j < 4; j++) acc[j] = make_float4(0.f, 0.f, 0.f, 0.f);

    const float tbase = tmn + (float)(4*sg) * DT_F;

    for (int k = 0; k < NK; k++) {
        __syncthreads();   // prior eval done (and Mc ready on first pass)
        // Stage prim k's template, transposing channels into float4-per-voxel
        const float* tk = tpl_g + (size_t)k * 4 * 4096;
        #pragma unroll
        for (int v = tid; v < 4096; v += NTHREADS) {
            tpl[v] = make_float4(tk[v], tk[v+4096], tk[v+8192], tk[v+12288]);
        }
        __syncthreads();

        const float m00 = Mc[12*k+0], m01 = Mc[12*k+1], m02 = Mc[12*k+2], c0 = Mc[12*k+3];
        const float m10 = Mc[12*k+4], m11 = Mc[12*k+5], m12 = Mc[12*k+6], c1 = Mc[12*k+7];
        const float m20 = Mc[12*k+8], m21 = Mc[12*k+9], m22 = Mc[12*k+10], c2 = Mc[12*k+11];

        #pragma unroll
        for (int j = 0; j < 4; j++) {
            const float t  = tbase + (float)j * DT_F;
            const float px = fmaf(rdx, t, rpx);
            const float py = fmaf(rdy, t, rpy);
            const float pz = fmaf(rdz, t, rpz);
            const float y0 = fmaf(m00, px, fmaf(m01, py, fmaf(m02, pz, -c0)));
            const float y1 = fmaf(m10, px, fmaf(m11, py, fmaf(m12, pz, -c1)));
            const float y2 = fmaf(m20, px, fmaf(m21, py, fmaf(m22, pz, -c2)));

            if (fabsf(y0) <= 1.f && fabsf(y1) <= 1.f && fabsf(y2) <= 1.f) {
                // g in [0, 15] when inside
                const float gz = fmaf(y0, 7.5f, 7.5f);
                const float gy = fmaf(y1, 7.5f, 7.5f);
                const float gx = fmaf(y2, 7.5f, 7.5f);
                const float fz0 = fminf(floorf(gz), 14.f);
                const float fy0 = fminf(floorf(gy), 14.f);
                const float fx0 = fminf(floorf(gx), 14.f);
                const int iz = (int)fz0, iy = (int)fy0, ix = (int)fx0;
                const float fz = fminf(gz - fz0, 1.f);
                const float fy = fminf(gy - fy0, 1.f);
                const float fx = fminf(gx - fx0, 1.f);

                const int base = (iz*16 + iy)*16 + ix;
                const float4 v000 = tpl[base],       v001 = tpl[base + 1];
                const float4 v010 = tpl[base + 16],  v011 = tpl[base + 17];
                const float4 v100 = tpl[base + 256], v101 = tpl[base + 257];
                const float4 v110 = tpl[base + 272], v111 = tpl[base + 273];

                const float wz0 = 1.f - fz, wy0 = 1.f - fy, wx0 = 1.f - fx;
                const float w00 = wz0*wy0, w01 = wz0*fy, w10 = fz*wy0, w11 = fz*fy;
                const float w000 = w00*wx0, w001 = w00*fx;
                const float w010 = w01*wx0, w011 = w01*fx;
                const float w100 = w10*wx0, w101 = w10*fx;
                const float w110 = w11*wx0, w111 = w11*fx;

                float ax = acc[j].x, ay = acc[j].y, az = acc[j].z, aw = acc[j].w;
                ax = fmaf(w000, v000.x, ax); ay = fmaf(w000, v000.y, ay);
                az = fmaf(w000, v000.z, az); aw = fmaf(w000, v000.w, aw);
                ax = fmaf(w001, v001.x, ax); ay = fmaf(w001, v001.y, ay);
                az = fmaf(w001, v001.z, az); aw = fmaf(w001, v001.w, aw);
                ax = fmaf(w010, v010.x, ax); ay = fmaf(w010, v010.y, ay);
                az = fmaf(w010, v010.z, az); aw = fmaf(w010, v010.w, aw);
                ax = fmaf(w011, v011.x, ax); ay = fmaf(w011, v011.y, ay);
                az = fmaf(w011, v011.z, az); aw = fmaf(w011, v011.w, aw);
                ax = fmaf(w100, v100.x, ax); ay = fmaf(w100, v100.y, ay);
                az = fmaf(w100, v100.z, az); aw = fmaf(w100, v100.w, aw);
                ax = fmaf(w101, v101.x, ax); ay = fmaf(w101, v101.y, ay);
                az = fmaf(w101, v101.z, az); aw = fmaf(w101, v101.w, aw);
                ax = fmaf(w110, v110.x, ax); ay = fmaf(w110, v110.y, ay);
                az = fmaf(w110, v110.z, az); aw = fmaf(w110, v110.w, aw);
                ax = fmaf(w111, v111.x, ax); ay = fmaf(w111, v111.y, ay);
                az = fmaf(w111, v111.z, az); aw = fmaf(w111, v111.w, aw);
                acc[j].x = ax; acc[j].y = ay; acc[j].z = az; acc[j].w = aw;
            }
        }
    }

    // ---- Composite: alpha_i = min(prefix_i, 1);  contrib_i = alpha_i - alpha_{i-1} ----
    float s0, s1, s2, s3;
    {
        const float t0 = tbase;
        const float t1 = tbase + DT_F;
        const float t2 = tbase + 2.f*DT_F;
        const float t3 = tbase + 3.f*DT_F;
        s0 = (t0 < tmx) ? acc[0].w * DT_F : 0.f;
        s1 = (t1 < tmx) ? acc[1].w * DT_F : 0.f;
        s2 = (t2 < tmx) ? acc[2].w * DT_F : 0.f;
        s3 = (t3 < tmx) ? acc[3].w * DT_F : 0.f;
    }
    // in-thread inclusive prefix
    const float p0 = s0;
    const float p1 = p0 + s1;
    const float p2 = p1 + s2;
    const float p3 = p2 + s3;
    const float tot = p3;

    // width-16 inclusive scan of per-thread totals (segments = rays)
    float scan = tot;
    #pragma unroll
    for (int d = 1; d < 16; d <<= 1) {
        const float v = __shfl_up_sync(0xffffffffu, scan, d, 16);
        if (sg >= d) scan += v;
    }
    const float excl = scan - tot;

    float aprev = fminf(excl, 1.f);
    float rgbx = 0.f, rgby = 0.f, rgbz = 0.f;
    {
        float P, al, contrib;
        P = excl + p0; al = fminf(P, 1.f); contrib = al - aprev; aprev = al;
        rgbx = fmaf(acc[0].x, contrib, rgbx); rgby = fmaf(acc[0].y, contrib, rgby); rgbz = fmaf(acc[0].z, contrib, rgbz);
        P = excl + p1; al = fminf(P, 1.f); contrib = al - aprev; aprev = al;
        rgbx = fmaf(acc[1].x, contrib, rgbx); rgby = fmaf(acc[1].y, contrib, rgby); rgbz = fmaf(acc[1].z, contrib, rgbz);
        P = excl + p2; al = fminf(P, 1.f); contrib = al - aprev; aprev = al;
        rgbx = fmaf(acc[2].x, contrib, rgbx); rgby = fmaf(acc[2].y, contrib, rgby); rgbz = fmaf(acc[2].z, contrib, rgbz);
        P = excl + p3; al = fminf(P, 1.f); contrib = al - aprev; aprev = al;
        rgbx = fmaf(acc[3].x, contrib, rgbx); rgby = fmaf(acc[3].y, contrib, rgby); rgbz = fmaf(acc[3].z, contrib, rgbz);
    }

    // width-16 reduction of rgb partials
    #pragma unroll
    for (int d = 8; d >= 1; d >>= 1) {
        rgbx += __shfl_xor_sync(0xffffffffu, rgbx, d, 16);
        rgby += __shfl_xor_sync(0xffffffffu, rgby, d, 16);
        rgbz += __shfl_xor_sync(0xffffffffu, rgbz, d, 16);
    }
    const float alpha_final = fminf(__shfl_sync(0xffffffffu, scan, 15, 16), 1.f);

    if (sg == 0) {
        // out = [rayrgb (3*R)] [rayalpha (R)] [rayrgba (4*R)]
        out[0*RTOT + r] = rgbx;
        out[1*RTOT + r] = rgby;
        out[2*RTOT + r] = rgbz;
        out[3*RTOT + r] = alpha_final;
        out[4*RTOT + r] = rgbx;
        out[5*RTOT + r] = rgby;
        out[6*RTOT + r] = rgbz;
        out[7*RTOT + r] = alpha_final;
    }
}

extern "C" void kernel_launch(void* const* d_in, const int* in_sizes, int n_in,
                              void* d_out, int out_size)
{
    const float* raypos    = (const float*)d_in[0];
    const float* raydir    = (const float*)d_in[1];
    const float* tminmax   = (const float*)d_in[2];
    const float* primpos   = (const float*)d_in[3];
    const float* primrot   = (const float*)d_in[4];
    const float* primscale = (const float*)d_in[5];
    const float* tpl       = (const float*)d_in[6];
    float* out = (float*)d_out;

    cudaFuncSetAttribute(raymarch_kernel,
                         cudaFuncAttributeMaxDynamicSharedMemorySize, SMEM_BYTES);

    raymarch_kernel<<<NBLOCKS, NTHREADS, SMEM_BYTES>>>(
        raypos, raydir, tminmax, primpos, primrot, primscale, tpl, out);
}

// round 4
// speedup vs baseline: 1.2590x; 1.2590x over previous
#include <cuda_runtime.h>
#include <cuda_fp16.h>
#include <cstdint>

#define DT_F (1.0f/64.0f)
#define NSTEPS 64
#define NK 32
#define RTOT 16384
#define RAYS_PER_BLOCK 64
#define NTHREADS 1024
#define NBLOCKS (RTOT / RAYS_PER_BLOCK)         // 256
#define VOX_PER_PRIM 4096
// dynamic smem: 2 x 4096 uint2 (fp16x4 voxels) + 32*12 floats affine
#define SMEM_BYTES (2 * VOX_PER_PRIM * 8 + NK * 12 * 4)

// fp16-packed template: [k][z][y][x] -> uint2 (r,g | b,a as half2)
__device__ uint2 g_tplh[NK * VOX_PER_PRIM];

__global__ void convert_tpl_kernel(const float* __restrict__ tpl)
{
    const int idx = blockIdx.x * blockDim.x + threadIdx.x;   // 0 .. 131071
    const int k = idx >> 12;
    const int v = idx & 4095;
    const float* tk = tpl + (size_t)k * 4 * VOX_PER_PRIM;
    const float r = tk[v];
    const float g = tk[v + 4096];
    const float b = tk[v + 8192];
    const float a = tk[v + 12288];
    const half2 h0 = __floats2half2_rn(r, g);
    const half2 h1 = __floats2half2_rn(b, a);
    uint2 q;
    q.x = *reinterpret_cast<const unsigned int*>(&h0);
    q.y = *reinterpret_cast<const unsigned int*>(&h1);
    g_tplh[idx] = q;
}

__device__ __forceinline__ void cp_async16(uint32_t saddr, const void* gaddr)
{
    asm volatile("cp.async.cg.shared.global [%0], [%1], 16;\n" :: "r"(saddr), "l"(gaddr));
}
__device__ __forceinline__ void cp_commit()  { asm volatile("cp.async.commit_group;\n" ::: "memory"); }
__device__ __forceinline__ void cp_wait0()   { asm volatile("cp.async.wait_group 0;\n" ::: "memory"); }

__device__ __forceinline__ void vox_unpack(const uint2 q, float& r, float& g, float& b, float& a)
{
    const half2 h0 = *reinterpret_cast<const half2*>(&q.x);
    const half2 h1 = *reinterpret_cast<const half2*>(&q.y);
    const float2 f0 = __half22float2(h0);
    const float2 f1 = __half22float2(h1);
    r = f0.x; g = f0.y; b = f1.x; a = f1.y;
}

__global__ void __launch_bounds__(NTHREADS, 1)
raymarch_kernel(const float* __restrict__ raypos,
                const float* __restrict__ raydir,
                const float* __restrict__ tminmax,
                const float* __restrict__ primpos,
                const float* __restrict__ primrot,
                const float* __restrict__ primscale,
                float* __restrict__ out)
{
    extern __shared__ uint2 smbuf[];                 // [2][4096]
    float* Mc = (float*)(smbuf + 2 * VOX_PER_PRIM);  // [32][12]

    const int tid  = threadIdx.x;
    const int sg   = tid & 15;             // step-group 0..15 (4 steps each)
    const int rayl = tid >> 4;             // local ray 0..63
    const int r    = blockIdx.x * RAYS_PER_BLOCK + rayl;

    const float rpx = raypos[3*r+0], rpy = raypos[3*r+1], rpz = raypos[3*r+2];
    const float rdx = raydir[3*r+0], rdy = raydir[3*r+1], rdz = raydir[3*r+2];
    const float tmn = tminmax[2*r+0], tmx = tminmax[2*r+1];

    // Per-prim affine: yloc_i = M[i]·pos - c_i, M[i][j] = scale_i * rot[i][j]
    if (tid < NK) {
        const int k = tid;
        const float ppx = primpos[3*k+0], ppy = primpos[3*k+1], ppz = primpos[3*k+2];
        #pragma unroll
        for (int i = 0; i < 3; i++) {
            const float s  = primscale[3*k+i];
            const float m0 = s * primrot[9*k+3*i+0];
            const float m1 = s * primrot[9*k+3*i+1];
            const float m2 = s * primrot[9*k+3*i+2];
            Mc[12*k+4*i+0] = m0;
            Mc[12*k+4*i+1] = m1;
            Mc[12*k+4*i+2] = m2;
            Mc[12*k+4*i+3] = m0*ppx + m1*ppy + m2*ppz;
        }
    }

    // Hoisted sample positions for the 4 steps owned by this thread
    const float tbase = tmn + (float)(4*sg) * DT_F;
    float px[4], py[4], pz[4];
    #pragma unroll
    for (int j = 0; j < 4; j++) {
        const float t = tbase + (float)j * DT_F;
        px[j] = fmaf(rdx, t, rpx);
        py[j] = fmaf(rdy, t, rpy);
        pz[j] = fmaf(rdz, t, rpz);
    }

    float4 acc[4];
    #pragma unroll
    for (int j = 0; j < 4; j++) acc[j] = make_float4(0.f, 0.f, 0.f, 0.f);

    const uint32_t sm_base = (uint32_t)__cvta_generic_to_shared(smbuf);

    // Prefetch prim 0 into buffer 0 (16B = 2 voxels per cp.async; 2048 chunks)
    {
        const uint2* src = g_tplh;                    // prim 0
        cp_async16(sm_base + (uint32_t)(tid * 16),              src + tid * 2);
        cp_async16(sm_base + (uint32_t)((tid + 1024) * 16),     src + (tid + 1024) * 2);
        cp_commit();
    }

    for (int k = 0; k < NK; k++) {
        const int cur = k & 1;
        cp_wait0();
        __syncthreads();   // buf[cur] fully staged; eval of buf[cur] (from k-1 round) done

        if (k + 1 < NK) {
            const uint2* src = g_tplh + (size_t)(k + 1) * VOX_PER_PRIM;
            const uint32_t dst = sm_base + (uint32_t)((k + 1) & 1) * (VOX_PER_PRIM * 8);
            cp_async16(dst + (uint32_t)(tid * 16),          src + tid * 2);
            cp_async16(dst + (uint32_t)((tid + 1024) * 16), src + (tid + 1024) * 2);
            cp_commit();
        }

        const uint2* __restrict__ tpl = smbuf + cur * VOX_PER_PRIM;

        const float m00 = Mc[12*k+0], m01 = Mc[12*k+1], m02 = Mc[12*k+2], c0 = Mc[12*k+3];
        const float m10 = Mc[12*k+4], m11 = Mc[12*k+5], m12 = Mc[12*k+6], c1 = Mc[12*k+7];
        const float m20 = Mc[12*k+8], m21 = Mc[12*k+9], m22 = Mc[12*k+10], c2 = Mc[12*k+11];

        #pragma unroll
        for (int j = 0; j < 4; j++) {
            const float y0 = fmaf(m00, px[j], fmaf(m01, py[j], fmaf(m02, pz[j], -c0)));
            const float y1 = fmaf(m10, px[j], fmaf(m11, py[j], fmaf(m12, pz[j], -c1)));
            const float y2 = fmaf(m20, px[j], fmaf(m21, py[j], fmaf(m22, pz[j], -c2)));

            if (fabsf(y0) <= 1.f && fabsf(y1) <= 1.f && fabsf(y2) <= 1.f) {
                const float gz = fmaf(y0, 7.5f, 7.5f);
                const float gy = fmaf(y1, 7.5f, 7.5f);
                const float gx = fmaf(y2, 7.5f, 7.5f);
                const float fz0 = fminf(floorf(gz), 14.f);
                const float fy0 = fminf(floorf(gy), 14.f);
                const float fx0 = fminf(floorf(gx), 14.f);
                const int iz = (int)fz0, iy = (int)fy0, ix = (int)fx0;
                const float fz = fminf(gz - fz0, 1.f);
                const float fy = fminf(gy - fy0, 1.f);
                const float fx = fminf(gx - fx0, 1.f);

                const int base = (iz*16 + iy)*16 + ix;
                const uint2 q000 = tpl[base],       q001 = tpl[base + 1];
                const uint2 q010 = tpl[base + 16],  q011 = tpl[base + 17];
                const uint2 q100 = tpl[base + 256], q101 = tpl[base + 257];
                const uint2 q110 = tpl[base + 272], q111 = tpl[base + 273];

                const float wz0 = 1.f - fz, wy0 = 1.f - fy, wx0 = 1.f - fx;
                const float w00 = wz0*wy0, w01 = wz0*fy, w10 = fz*wy0, w11 = fz*fy;
                const float w000 = w00*wx0, w001 = w00*fx;
                const float w010 = w01*wx0, w011 = w01*fx;
                const float w100 = w10*wx0, w101 = w10*fx;
                const float w110 = w11*wx0, w111 = w11*fx;

                float vr, vg, vb, va;
                float ax = acc[j].x, ay = acc[j].y, az = acc[j].z, aw = acc[j].w;
                vox_unpack(q000, vr, vg, vb, va);
                ax = fmaf(w000, vr, ax); ay = fmaf(w000, vg, ay);
                az = fmaf(w000, vb, az); aw = fmaf(w000, va, aw);
                vox_unpack(q001, vr, vg, vb, va);
                ax = fmaf(w001, vr, ax); ay = fmaf(w001, vg, ay);
                az = fmaf(w001, vb, az); aw = fmaf(w001, va, aw);
                vox_unpack(q010, vr, vg, vb, va);
                ax = fmaf(w010, vr, ax); ay = fmaf(w010, vg, ay);
                az = fmaf(w010, vb, az); aw = fmaf(w010, va, aw);
                vox_unpack(q011, vr, vg, vb, va);
                ax = fmaf(w011, vr, ax); ay = fmaf(w011, vg, ay);
                az = fmaf(w011, vb, az); aw = fmaf(w011, va, aw);
                vox_unpack(q100, vr, vg, vb, va);
                ax = fmaf(w100, vr, ax); ay = fmaf(w100, vg, ay);
                az = fmaf(w100, vb, az); aw = fmaf(w100, va, aw);
                vox_unpack(q101, vr, vg, vb, va);
                ax = fmaf(w101, vr, ax); ay = fmaf(w101, vg, ay);
                az = fmaf(w101, vb, az); aw = fmaf(w101, va, aw);
                vox_unpack(q110, vr, vg, vb, va);
                ax = fmaf(w110, vr, ax); ay = fmaf(w110, vg, ay);
                az = fmaf(w110, vb, az); aw = fmaf(w110, va, aw);
                vox_unpack(q111, vr, vg, vb, va);
                ax = fmaf(w111, vr, ax); ay = fmaf(w111, vg, ay);
                az = fmaf(w111, vb, az); aw = fmaf(w111, va, aw);
                acc[j].x = ax; acc[j].y = ay; acc[j].z = az; acc[j].w = aw;
            }
        }
        __syncthreads();   // everyone done with buf[cur] before it is refilled (k+2)
    }

    // ---- Composite: alpha_i = min(prefix_i, 1);  contrib_i = alpha_i - alpha_{i-1} ----
    float s0, s1, s2, s3;
    {
        const float t0 = tbase;
        const float t1 = tbase + DT_F;
        const float t2 = tbase + 2.f*DT_F;
        const float t3 = tbase + 3.f*DT_F;
        s0 = (t0 < tmx) ? acc[0].w * DT_F : 0.f;
        s1 = (t1 < tmx) ? acc[1].w * DT_F : 0.f;
        s2 = (t2 < tmx) ? acc[2].w * DT_F : 0.f;
        s3 = (t3 < tmx) ? acc[3].w * DT_F : 0.f;
    }
    const float p0 = s0;
    const float p1 = p0 + s1;
    const float p2 = p1 + s2;
    const float p3 = p2 + s3;
    const float tot = p3;

    // width-16 inclusive scan of per-thread totals (segments = rays)
    float scan = tot;
    #pragma unroll
    for (int d = 1; d < 16; d <<= 1) {
        const float v = __shfl_up_sync(0xffffffffu, scan, d, 16);
        if (sg >= d) scan += v;
    }
    const float excl = scan - tot;

    float aprev = fminf(excl, 1.f);
    float rgbx = 0.f, rgby = 0.f, rgbz = 0.f;
    {
        float P, al, contrib;
        P = excl + p0; al = fminf(P, 1.f); contrib = al - aprev; aprev = al;
        rgbx = fmaf(acc[0].x, contrib, rgbx); rgby = fmaf(acc[0].y, contrib, rgby); rgbz = fmaf(acc[0].z, contrib, rgbz);
        P = excl + p1; al = fminf(P, 1.f); contrib = al - aprev; aprev = al;
        rgbx = fmaf(acc[1].x, contrib, rgbx); rgby = fmaf(acc[1].y, contrib, rgby); rgbz = fmaf(acc[1].z, contrib, rgbz);
        P = excl + p2; al = fminf(P, 1.f); contrib = al - aprev; aprev = al;
        rgbx = fmaf(acc[2].x, contrib, rgbx); rgby = fmaf(acc[2].y, contrib, rgby); rgbz = fmaf(acc[2].z, contrib, rgbz);
        P = excl + p3; al = fminf(P, 1.f); contrib = al - aprev; aprev = al;
        rgbx = fmaf(acc[3].x, contrib, rgbx); rgby = fmaf(acc[3].y, contrib, rgby); rgbz = fmaf(acc[3].z, contrib, rgbz);
    }

    #pragma unroll
    for (int d = 8; d >= 1; d >>= 1) {
        rgbx += __shfl_xor_sync(0xffffffffu, rgbx, d, 16);
        rgby += __shfl_xor_sync(0xffffffffu, rgby, d, 16);
        rgbz += __shfl_xor_sync(0xffffffffu, rgbz, d, 16);
    }
    const float alpha_final = fminf(__shfl_sync(0xffffffffu, scan, 15, 16), 1.f);

    if (sg == 0) {
        // out = [rayrgb (3*R)] [rayalpha (R)] [rayrgba (4*R)]
        out[0*RTOT + r] = rgbx;
        out[1*RTOT + r] = rgby;
        out[2*RTOT + r] = rgbz;
        out[3*RTOT + r] = alpha_final;
        out[4*RTOT + r] = rgbx;
        out[5*RTOT + r] = rgby;
        out[6*RTOT + r] = rgbz;
        out[7*RTOT + r] = alpha_final;
    }
}

extern "C" void kernel_launch(void* const* d_in, const int* in_sizes, int n_in,
                              void* d_out, int out_size)
{
    const float* raypos    = (const float*)d_in[0];
    const float* raydir    = (const float*)d_in[1];
    const float* tminmax   = (const float*)d_in[2];
    const float* primpos   = (const float*)d_in[3];
    const float* primrot   = (const float*)d_in[4];
    const float* primscale = (const float*)d_in[5];
    const float* tpl       = (const float*)d_in[6];
    float* out = (float*)d_out;

    convert_tpl_kernel<<<NK * VOX_PER_PRIM / 256, 256>>>(tpl);

    cudaFuncSetAttribute(raymarch_kernel,
                         cudaFuncAttributeMaxDynamicSharedMemorySize, SMEM_BYTES);

    raymarch_kernel<<<NBLOCKS, NTHREADS, SMEM_BYTES>>>(
        raypos, raydir, tminmax, primpos, primrot, primscale, out);
}